// round 1
// baseline (speedup 1.0000x reference)
#include <cuda_runtime.h>
#include <cuda_fp16.h>

// LIF spike neuron scan.
// x: [B,S,N] fp32, m0: [B,N] fp32.
// out (fp32): spikes [B,S,N] flattened, then m_final [B,N].
// B=32, S=1024, N=2048.

#define B_DIM 32
#define S_DIM 1024
#define N_DIM 2048
#define DECAY 0.8f
#define THRESH 0.5f
#define UNROLL 8

__global__ __launch_bounds__(256) void lif_scan_kernel(
    const float* __restrict__ x,
    const float* __restrict__ m0,
    float* __restrict__ out)
{
    const int idx = blockIdx.x * blockDim.x + threadIdx.x;  // b*N + n
    if (idx >= B_DIM * N_DIM) return;

    const int b = idx >> 11;           // /N_DIM
    const int n = idx & (N_DIM - 1);   // %N_DIM

    const size_t base = (size_t)b * S_DIM * N_DIM + n;
    const float* __restrict__ xp = x + base;
    float* __restrict__ sp = out + base;                       // spikes region
    float* __restrict__ mfin = out + (size_t)B_DIM * S_DIM * N_DIM;  // m_final region

    float m = m0[idx];

    #pragma unroll 1
    for (int t = 0; t < S_DIM; t += UNROLL) {
        float xv[UNROLL];
        // Front-batched loads: independent of the recurrence -> MLP=UNROLL
        #pragma unroll
        for (int k = 0; k < UNROLL; k++)
            xv[k] = xp[(size_t)(t + k) * N_DIM];

        #pragma unroll
        for (int k = 0; k < UNROLL; k++) {
            m = DECAY * m + xv[k];
            const bool fire = (m > THRESH);
            sp[(size_t)(t + k) * N_DIM] = fire ? 1.0f : 0.0f;
            m = fire ? 0.0f : m;
        }
    }

    mfin[idx] = m;
}

extern "C" void kernel_launch(void* const* d_in, const int* in_sizes, int n_in,
                              void* d_out, int out_size)
{
    const float* x  = (const float*)d_in[0];
    const float* m0 = (const float*)d_in[1];
    float* out = (float*)d_out;

    const int total = B_DIM * N_DIM;           // 65536 threads
    const int threads = 256;
    const int blocks = (total + threads - 1) / threads;
    lif_scan_kernel<<<blocks, threads>>>(x, m0, out);
}

// round 2
// speedup vs baseline: 1.2352x; 1.2352x over previous
#include <cuda_runtime.h>
#include <cuda_fp16.h>

// LIF spike neuron scan.
// x: [B,S,N] fp32, m0: [B,N] fp32.
// out (fp32): spikes [B,S,N] flattened, then m_final [B,N].
// B=32, S=1024, N=2048.

#define B_DIM 32
#define S_DIM 1024
#define N_DIM 2048
#define DECAY 0.8f
#define THRESH 0.5f
#define UNROLL 16

__global__ __launch_bounds__(256) void lif_scan_kernel(
    const float* __restrict__ x,
    const float* __restrict__ m0,
    float* __restrict__ out)
{
    const int idx = blockIdx.x * blockDim.x + threadIdx.x;  // b*N + n
    if (idx >= B_DIM * N_DIM) return;

    const int b = idx >> 11;           // /N_DIM
    const int n = idx & (N_DIM - 1);   // %N_DIM

    const size_t base = (size_t)b * S_DIM * N_DIM + n;
    const float* __restrict__ xp = x + base;
    float* __restrict__ sp = out + base;                             // spikes region
    float* __restrict__ mfin = out + (size_t)B_DIM * S_DIM * N_DIM;  // m_final region

    float m = m0[idx];

    #pragma unroll 1
    for (int t = 0; t < S_DIM; t += UNROLL) {
        float xv[UNROLL];
        // Front-batched streaming loads: 16 independent LDGs in flight per thread.
        #pragma unroll
        for (int k = 0; k < UNROLL; k++)
            xv[k] = __ldcs(xp + (size_t)(t + k) * N_DIM);

        #pragma unroll
        for (int k = 0; k < UNROLL; k++) {
            m = DECAY * m + xv[k];
            const bool fire = (m > THRESH);
            __stcs(sp + (size_t)(t + k) * N_DIM, fire ? 1.0f : 0.0f);
            m = fire ? 0.0f : m;
        }
    }

    mfin[idx] = m;
}

extern "C" void kernel_launch(void* const* d_in, const int* in_sizes, int n_in,
                              void* d_out, int out_size)
{
    const float* x  = (const float*)d_in[0];
    const float* m0 = (const float*)d_in[1];
    float* out = (float*)d_out;

    const int total = B_DIM * N_DIM;           // 65536 threads
    const int threads = 256;
    const int blocks = (total + threads - 1) / threads;
    lif_scan_kernel<<<blocks, threads>>>(x, m0, out);
}

// round 3
// speedup vs baseline: 1.2847x; 1.0401x over previous
#include <cuda_runtime.h>
#include <cuda_fp16.h>

// LIF spike neuron scan — register-double-buffered streaming version.
// x: [B,S,N] fp32, m0: [B,N] fp32.
// out (fp32): spikes [B,S,N] flattened, then m_final [B,N].
// B=32, S=1024, N=2048.

#define B_DIM 32
#define S_DIM 1024
#define N_DIM 2048
#define DECAY 0.8f
#define THRESH 0.5f
#define U 8   // timesteps per pipeline stage

__global__ __launch_bounds__(64) void lif_scan_kernel(
    const float* __restrict__ x,
    const float* __restrict__ m0,
    float* __restrict__ out)
{
    const int idx = blockIdx.x * blockDim.x + threadIdx.x;  // b*N + n
    if (idx >= B_DIM * N_DIM) return;

    const int b = idx >> 11;           // /N_DIM
    const int n = idx & (N_DIM - 1);   // %N_DIM

    const size_t base = (size_t)b * S_DIM * N_DIM + n;
    const float* __restrict__ xp = x + base;
    float* __restrict__ sp = out + base;                             // spikes region
    float* __restrict__ mfin = out + (size_t)B_DIM * S_DIM * N_DIM;  // m_final region

    float m = m0[idx];

    float a[U], bb[U];

    // Prologue: load stage 0
    #pragma unroll
    for (int k = 0; k < U; k++)
        a[k] = __ldcs(xp + (size_t)k * N_DIM);

    #pragma unroll 1
    for (int t = 0; t < S_DIM; t += 2 * U) {
        // Prefetch stage t+U while computing stage t
        #pragma unroll
        for (int k = 0; k < U; k++)
            bb[k] = __ldcs(xp + (size_t)(t + U + k) * N_DIM);

        #pragma unroll
        for (int k = 0; k < U; k++) {
            m = DECAY * m + a[k];
            const bool fire = (m > THRESH);
            __stcs(sp + (size_t)(t + k) * N_DIM, fire ? 1.0f : 0.0f);
            m = fire ? 0.0f : m;
        }

        // Prefetch stage t+2U (guarded) while computing stage t+U
        if (t + 2 * U < S_DIM) {
            #pragma unroll
            for (int k = 0; k < U; k++)
                a[k] = __ldcs(xp + (size_t)(t + 2 * U + k) * N_DIM);
        }

        #pragma unroll
        for (int k = 0; k < U; k++) {
            m = DECAY * m + bb[k];
            const bool fire = (m > THRESH);
            __stcs(sp + (size_t)(t + U + k) * N_DIM, fire ? 1.0f : 0.0f);
            m = fire ? 0.0f : m;
        }
    }

    mfin[idx] = m;
}

extern "C" void kernel_launch(void* const* d_in, const int* in_sizes, int n_in,
                              void* d_out, int out_size)
{
    const float* x  = (const float*)d_in[0];
    const float* m0 = (const float*)d_in[1];
    float* out = (float*)d_out;

    const int total = B_DIM * N_DIM;   // 65536 threads
    const int threads = 64;            // small blocks -> even per-SM CTA distribution
    const int blocks = (total + threads - 1) / threads;  // 1024
    lif_scan_kernel<<<blocks, threads>>>(x, m0, out);
}

// round 4
// speedup vs baseline: 1.4648x; 1.1402x over previous
#include <cuda_runtime.h>
#include <cuda_fp16.h>

// LIF spike neuron scan — deep register-double-buffered streaming version.
// x: [B,S,N] fp32, m0: [B,N] fp32.
// out (fp32): spikes [B,S,N] flattened, then m_final [B,N].
// B=32, S=1024, N=2048.

#define B_DIM 32
#define S_DIM 1024
#define N_DIM 2048
#define DECAY 0.8f
#define THRESH 0.5f
#define U 16   // timesteps per pipeline stage (16 LDG in flight through compute)

__global__ __launch_bounds__(64) void lif_scan_kernel(
    const float* __restrict__ x,
    const float* __restrict__ m0,
    float* __restrict__ out)
{
    const int idx = blockIdx.x * blockDim.x + threadIdx.x;  // b*N + n
    if (idx >= B_DIM * N_DIM) return;

    const int b = idx >> 11;           // /N_DIM
    const int n = idx & (N_DIM - 1);   // %N_DIM

    const size_t base = (size_t)b * S_DIM * N_DIM + n;
    const float* __restrict__ xp = x + base;
    float* __restrict__ sp = out + base;                             // spikes region
    float* __restrict__ mfin = out + (size_t)B_DIM * S_DIM * N_DIM;  // m_final region

    float m = m0[idx];

    float a[U], bb[U];

    // Prologue: load stage 0
    #pragma unroll
    for (int k = 0; k < U; k++)
        a[k] = __ldcs(xp + (size_t)k * N_DIM);

    #pragma unroll 1
    for (int t = 0; t < S_DIM; t += 2 * U) {
        // Prefetch stage t+U while computing stage t
        #pragma unroll
        for (int k = 0; k < U; k++)
            bb[k] = __ldcs(xp + (size_t)(t + U + k) * N_DIM);

        #pragma unroll
        for (int k = 0; k < U; k++) {
            m = DECAY * m + a[k];
            const bool fire = (m > THRESH);
            __stcs(sp + (size_t)(t + k) * N_DIM, fire ? 1.0f : 0.0f);
            m = fire ? 0.0f : m;
        }

        // Prefetch stage t+2U (guarded) while computing stage t+U
        if (t + 2 * U < S_DIM) {
            #pragma unroll
            for (int k = 0; k < U; k++)
                a[k] = __ldcs(xp + (size_t)(t + 2 * U + k) * N_DIM);
        }

        #pragma unroll
        for (int k = 0; k < U; k++) {
            m = DECAY * m + bb[k];
            const bool fire = (m > THRESH);
            __stcs(sp + (size_t)(t + U + k) * N_DIM, fire ? 1.0f : 0.0f);
            m = fire ? 0.0f : m;
        }
    }

    mfin[idx] = m;
}

extern "C" void kernel_launch(void* const* d_in, const int* in_sizes, int n_in,
                              void* d_out, int out_size)
{
    const float* x  = (const float*)d_in[0];
    const float* m0 = (const float*)d_in[1];
    float* out = (float*)d_out;

    const int total = B_DIM * N_DIM;   // 65536 threads
    const int threads = 64;            // small blocks -> even per-SM CTA distribution
    const int blocks = (total + threads - 1) / threads;  // 1024
    lif_scan_kernel<<<blocks, threads>>>(x, m0, out);
}

// round 5
// speedup vs baseline: 1.4880x; 1.0159x over previous
#include <cuda_runtime.h>
#include <cuda_fp16.h>

// LIF spike neuron scan — U=32 register-double-buffered streaming version.
// x: [B,S,N] fp32, m0: [B,N] fp32.
// out (fp32): spikes [B,S,N] flattened, then m_final [B,N].
// B=32, S=1024, N=2048.

#define B_DIM 32
#define S_DIM 1024
#define N_DIM 2048
#define DECAY 0.8f
#define THRESH 0.5f
#define U 32   // timesteps per pipeline stage (32 LDG sustained in flight)

__global__ __launch_bounds__(64) void lif_scan_kernel(
    const float* __restrict__ x,
    const float* __restrict__ m0,
    float* __restrict__ out)
{
    const int idx = blockIdx.x * blockDim.x + threadIdx.x;  // b*N + n
    if (idx >= B_DIM * N_DIM) return;

    const int b = idx >> 11;           // /N_DIM
    const int n = idx & (N_DIM - 1);   // %N_DIM

    const size_t base = (size_t)b * S_DIM * N_DIM + n;
    const float* __restrict__ xp = x + base;
    float* __restrict__ sp = out + base;                             // spikes region
    float* __restrict__ mfin = out + (size_t)B_DIM * S_DIM * N_DIM;  // m_final region

    float m = m0[idx];

    float a[U], bb[U];

    // Prologue: load stage 0
    #pragma unroll
    for (int k = 0; k < U; k++)
        a[k] = __ldcs(xp + (size_t)k * N_DIM);

    #pragma unroll 1
    for (int t = 0; t < S_DIM; t += 2 * U) {
        // Prefetch stage t+U while computing stage t
        #pragma unroll
        for (int k = 0; k < U; k++)
            bb[k] = __ldcs(xp + (size_t)(t + U + k) * N_DIM);

        #pragma unroll
        for (int k = 0; k < U; k++) {
            m = DECAY * m + a[k];
            const bool fire = (m > THRESH);
            __stcs(sp + (size_t)(t + k) * N_DIM, fire ? 1.0f : 0.0f);
            m = fire ? 0.0f : m;
        }

        // Prefetch stage t+2U (guarded) while computing stage t+U
        if (t + 2 * U < S_DIM) {
            #pragma unroll
            for (int k = 0; k < U; k++)
                a[k] = __ldcs(xp + (size_t)(t + 2 * U + k) * N_DIM);
        }

        #pragma unroll
        for (int k = 0; k < U; k++) {
            m = DECAY * m + bb[k];
            const bool fire = (m > THRESH);
            __stcs(sp + (size_t)(t + U + k) * N_DIM, fire ? 1.0f : 0.0f);
            m = fire ? 0.0f : m;
        }
    }

    mfin[idx] = m;
}

extern "C" void kernel_launch(void* const* d_in, const int* in_sizes, int n_in,
                              void* d_out, int out_size)
{
    const float* x  = (const float*)d_in[0];
    const float* m0 = (const float*)d_in[1];
    float* out = (float*)d_out;

    const int total = B_DIM * N_DIM;   // 65536 threads
    const int threads = 64;            // small blocks -> even per-SM CTA distribution
    const int blocks = (total + threads - 1) / threads;  // 1024
    lif_scan_kernel<<<blocks, threads>>>(x, m0, out);
}